// round 10
// baseline (speedup 1.0000x reference)
#include <cuda_runtime.h>
#include <stdint.h>

// WeightedHashEmbedding, persistent-grid, depth-2 software pipeline:
//   out[b, d] = (1/32) * sum_{c=0..31} table[idx0[b,c], d] * weights[idx1[b,c]]
//
// R7 config (proven optimum: 1 row/warp, float2 lanes, 32 LDG.64 entries/warp)
// plus a deeper prefetch pipeline: indices loaded 2 rows ahead, the dependent
// weight gather 1 row ahead — the serial idx1->weight chain (~1150 cyc) gets
// a full row-iteration of slack instead of racing the current row's window.

#define B_ROWS   32768
#define N_CHUNKS 32
#define DIM      64
#define NUM_SMS  148
#define BLOCKS_PER_SM 4

__device__ __forceinline__ void stcs_f2(float2* p, float2 v) {
    asm volatile("st.global.cs.v2.f32 [%0], {%1,%2};" :: "l"(p), "f"(v.x), "f"(v.y));
}

__global__ void __launch_bounds__(256, BLOCKS_PER_SM)
whe_kernel(const float* __restrict__ table,
           const float* __restrict__ weights,
           const int*   __restrict__ idx0,
           const int*   __restrict__ idx1,
           float2*      __restrict__ out)
{
    const int lane        = threadIdx.x & 31;
    const int warp_global = blockIdx.x * (blockDim.x >> 5) + (threadIdx.x >> 5);
    const int total_warps = gridDim.x * (blockDim.x >> 5);   // 4736

    int b = warp_global;

    // ---- Pipeline prologue ----
    // Stage 0 (row b): idx + weight resolved.
    int   i0_cur = 0;
    float wv_cur = 0.0f;
    // Stage 1 (row b+S): idx loaded, weight in flight.
    int   i0_nxt = 0, i1_nxt = 0;
    float wv_nxt = 0.0f;

    if (b < B_ROWS) {
        i0_cur = __ldcs(idx0 + b * N_CHUNKS + lane);
        const int i1c = __ldcs(idx1 + b * N_CHUNKS + lane);
        wv_cur = __ldcs(weights + (uint32_t)i1c) * (1.0f / N_CHUNKS);
    }
    {
        const int b1 = b + total_warps;
        if (b1 < B_ROWS) {
            i0_nxt = __ldcs(idx0 + b1 * N_CHUNKS + lane);
            i1_nxt = __ldcs(idx1 + b1 * N_CHUNKS + lane);
            wv_nxt = __ldcs(weights + (uint32_t)i1_nxt) * (1.0f / N_CHUNKS);
        }
    }

    while (b < B_ROWS) {
        const int   ci0 = i0_cur;
        const float cwv = wv_cur;
        const int   b2  = b + 2 * total_warps;

        // Rotate stage 1 -> stage 0.
        i0_cur = i0_nxt;
        wv_cur = wv_nxt;

        // Issue stage-2 idx loads + stage-1... (idx two rows ahead; its
        // dependent weight gather gets issued next iteration with a full
        // row of slack). Here: load idx(b+2) and weight(b+2) immediately —
        // idx(b+2) was NOT yet loaded, so split: idx now, weight depends on
        // it but has ~2 row-iterations (~4000 cyc) before use.
        if (b2 < B_ROWS) {
            i0_nxt = __ldcs(idx0 + b2 * N_CHUNKS + lane);
            i1_nxt = __ldcs(idx1 + b2 * N_CHUNKS + lane);
            wv_nxt = __ldcs(weights + (uint32_t)i1_nxt) * (1.0f / N_CHUNKS);
        }

        // ---- Current row: 32 independent table gathers ----
        float2 acc = make_float2(0.0f, 0.0f);

        #pragma unroll
        for (int c = 0; c < N_CHUNKS; ++c) {
            const int   t = __shfl_sync(0xffffffffu, ci0, c);
            const float w = __shfl_sync(0xffffffffu, cwv, c);
            const float2 v = __ldg(((const float2*)(table + (size_t)t * DIM)) + lane);
            acc.x = fmaf(v.x, w, acc.x);
            acc.y = fmaf(v.y, w, acc.y);
        }

        stcs_f2(out + b * 32 + lane, acc);

        b += total_warps;
    }
}

extern "C" void kernel_launch(void* const* d_in, const int* in_sizes, int n_in,
                              void* d_out, int out_size)
{
    const float* table   = (const float*)d_in[0];
    const float* weights = (const float*)d_in[1];
    const int*   idx0    = (const int*)d_in[2];
    const int*   idx1    = (const int*)d_in[3];
    float2*      out     = (float2*)d_out;

    const int threads = 256;                       // 8 warps/block
    const int blocks  = NUM_SMS * BLOCKS_PER_SM;   // 592 — exactly resident
    whe_kernel<<<blocks, threads>>>(table, weights, idx0, idx1, out);
}

// round 11
// speedup vs baseline: 1.0397x; 1.0397x over previous
#include <cuda_runtime.h>
#include <stdint.h>

// WeightedHashEmbedding — final-form candidate:
//   out[b, d] = (1/32) * sum_{c=0..31} table[idx0[b,c], d] * weights[idx1[b,c]]
//
// Combination of the two 57.5-57.9us parents:
//   R3 shape: one warp per output row, one-shot grid (4096 blocks),
//             low register count -> occ ~87%, 32 LDG.64 entries/warp (optimal).
//   R7 diet:  __ldcs on one-shot idx streams, weight gather prefetched off the
//             critical path and pre-scaled by 1/32, streaming v2 output store
//             (no L2 write-allocate).
// Everything else (wider loads, multi-row warps, deeper pipelines, phase
// splits, cache policies) measured and rejected R4-R10.

#define B_ROWS   32768
#define N_CHUNKS 32
#define DIM      64

__device__ __forceinline__ void stcs_f2(float2* p, float2 v) {
    asm volatile("st.global.cs.v2.f32 [%0], {%1,%2};" :: "l"(p), "f"(v.x), "f"(v.y));
}

__global__ void __launch_bounds__(256)
whe_kernel(const float* __restrict__ table,
           const float* __restrict__ weights,
           const int*   __restrict__ idx0,
           const int*   __restrict__ idx1,
           float2*      __restrict__ out)
{
    const int b    = blockIdx.x * (blockDim.x >> 5) + (threadIdx.x >> 5);
    const int lane = threadIdx.x & 31;
    if (b >= B_ROWS) return;

    // Coalesced, one-shot index streams: lane c holds chunk c's indices.
    const int i0 = __ldcs(idx0 + b * N_CHUNKS + lane);
    const int i1 = __ldcs(idx1 + b * N_CHUNKS + lane);

    // All 32 weight gathers issued as one divergent streaming load, off the
    // accumulation critical path; fold the mean's 1/32 in here.
    const float wv_lane = __ldcs(weights + (uint32_t)i1) * (1.0f / N_CHUNKS);

    float2 acc = make_float2(0.0f, 0.0f);

    #pragma unroll
    for (int c = 0; c < N_CHUNKS; ++c) {
        const int   t = __shfl_sync(0xffffffffu, i0, c);
        const float w = __shfl_sync(0xffffffffu, wv_lane, c);
        const float2 v = __ldg(((const float2*)(table + (size_t)t * DIM)) + lane);
        acc.x = fmaf(v.x, w, acc.x);
        acc.y = fmaf(v.y, w, acc.y);
    }

    // Streaming store: written once, never re-read.
    stcs_f2(out + b * 32 + lane, acc);
}

extern "C" void kernel_launch(void* const* d_in, const int* in_sizes, int n_in,
                              void* d_out, int out_size)
{
    const float* table   = (const float*)d_in[0];
    const float* weights = (const float*)d_in[1];
    const int*   idx0    = (const int*)d_in[2];
    const int*   idx1    = (const int*)d_in[3];
    float2*      out     = (float2*)d_out;

    const int threads = 256;                     // 8 warps -> 8 rows/block
    const int blocks  = B_ROWS / (threads / 32); // 4096
    whe_kernel<<<blocks, threads>>>(table, weights, idx0, idx1, out);
}